// round 2
// baseline (speedup 1.0000x reference)
#include <cuda_runtime.h>

#define SEQ  256
#define HID  2048
#define DIM  2048
#define GAT  8192   // 4*HID
#define NCTA 128
#define NTHR 1024
#define UPC  16     // hidden units owned per CTA (128*16 = 2048)

// ---- persistent device state (static allocation: allowed) ----
__device__ float g_Wt[(size_t)DIM * GAT];   // W_ih transposed: [DIM][GAT], 64MB
__device__ float g_h[HID];
__device__ float g_x[DIM];
__device__ unsigned int g_bar;
__device__ volatile unsigned int g_gen;

// ---- JAX threefry2x32 (exact rounds) ----
__device__ __forceinline__ void tf2x32(unsigned k0, unsigned k1,
                                       unsigned x0, unsigned x1,
                                       unsigned &o0, unsigned &o1) {
  unsigned ks2 = k0 ^ k1 ^ 0x1BD11BDAu;
#define TFR(r) { x0 += x1; x1 = (x1 << (r)) | (x1 >> (32 - (r))); x1 ^= x0; }
  x0 += k0; x1 += k1;
  TFR(13) TFR(15) TFR(26) TFR(6)   x0 += k1;  x1 += ks2 + 1u;
  TFR(17) TFR(29) TFR(16) TFR(24)  x0 += ks2; x1 += k0 + 2u;
  TFR(13) TFR(15) TFR(26) TFR(6)   x0 += k0;  x1 += k1 + 3u;
  TFR(17) TFR(29) TFR(16) TFR(24)  x0 += k1;  x1 += ks2 + 4u;
  TFR(13) TFR(15) TFR(26) TFR(6)   x0 += ks2; x1 += k0 + 5u;
#undef TFR
  o0 = x0; o1 = x1;
}

__device__ __forceinline__ float u01(unsigned bits) {
  return __uint_as_float((bits >> 9) | 0x3f800000u) - 1.0f;
}

__device__ __forceinline__ float sigf(float v) {
  return 1.0f / (1.0f + expf(-v));
}

// generation-based grid barrier (all CTAs co-resident by construction)
__device__ __forceinline__ void grid_barrier() {
  __threadfence();
  __syncthreads();
  if (threadIdx.x == 0) {
    unsigned gen = g_gen;
    if (atomicAdd(&g_bar, 1u) == gridDim.x - 1u) {
      g_bar = 0u;
      __threadfence();
      g_gen = gen + 1u;
    } else {
      while (g_gen == gen) { __nanosleep(20); }
    }
  }
  __syncthreads();
}

extern "C" __global__ void __launch_bounds__(NTHR, 1)
lstm_policy_kernel(const float* __restrict__ A,
                   const float* __restrict__ W_ih,
                   const float* __restrict__ W_hh,
                   const float* __restrict__ b_ih,
                   const float* __restrict__ b_hh,
                   const float* __restrict__ V_w,
                   const float* __restrict__ V_b,
                   const float* __restrict__ temp,
                   float* __restrict__ out)
{
  const int b    = blockIdx.x;
  const int tid  = threadIdx.x;
  const int lane = tid & 31;
  const int w    = tid >> 5;

  __shared__ float h_s[HID];          // 8KB
  __shared__ float x_s[DIM];          // 8KB
  __shared__ float gsum[64];          // gate pre-activations for owned units
  __shared__ float c_s[UPC];          // persistent cell state (owned units)
  __shared__ float part[16][64];      // deterministic phase-B reduction
  __shared__ float tile[32][33];      // transpose staging

  // ---- one-time (per launch) transpose W_ih[GAT][DIM] -> g_Wt[DIM][GAT] ----
  {
    const int ty = tid >> 5, tx = tid & 31;
    const int ntiles = (GAT / 32) * (DIM / 32);  // 16384
    for (int t = b; t < ntiles; t += gridDim.x) {
      int tr = t / (DIM / 32), tc = t % (DIM / 32);
      int r0 = tr * 32, j0 = tc * 32;
      tile[ty][tx] = W_ih[(size_t)(r0 + ty) * DIM + (j0 + tx)];
      __syncthreads();
      g_Wt[(size_t)(j0 + ty) * GAT + (r0 + tx)] = tile[tx][ty];
      __syncthreads();
    }
  }
  if (tid < UPC) c_s[tid] = 0.0f;
  grid_barrier();

  const float temperature = __ldg(temp);

  for (int step = 0; step < SEQ; ++step) {
    // per-step subkey (partitionable split): keys[t] = threefry(key, (0, t))
    unsigned sk0, sk1;
    tf2x32(0u, 42u, 0u, (unsigned)step, sk0, sk1);

    // =========== Phase A: z = V_w@h (owned 16 rows) ; gates_hh = W_hh@h (owned 64 rows) ===========
    for (int i = tid; i < HID; i += NTHR)
      h_s[i] = (step == 0) ? 0.0f : __ldcg(&g_h[i]);
    __syncthreads();

    const float4* H4 = (const float4*)h_s;
    for (int li = w; li < 80; li += 32) {
      const float* rowp;
      if (li < 16) {
        rowp = V_w + (size_t)(b * 16 + li) * DIM;
      } else {
        int gi = li - 16;
        int q = gi >> 4, i2 = gi & 15;
        rowp = W_hh + (size_t)(q * HID + b * 16 + i2) * DIM;
      }
      const float4* R4 = (const float4*)rowp;
      float s = 0.0f;
      #pragma unroll
      for (int k = 0; k < 16; ++k) {
        float4 a  = __ldg(&R4[k * 32 + lane]);
        float4 hh = H4[k * 32 + lane];
        s += a.x * hh.x + a.y * hh.y + a.z * hh.z + a.w * hh.w;
      }
      #pragma unroll
      for (int o = 16; o > 0; o >>= 1) s += __shfl_xor_sync(0xffffffffu, s, o);

      if (lane == 0) {
        if (li < 16) {
          // policy head: pi, bernoulli action via partitionable threefry:
          //   bits[r] = y0 ^ y1 of threefry(subkey, (0, r))
          int r = b * 16 + li;
          float z  = temperature * (s + __ldg(&V_b[r]));
          float pi = sigf(z);
          unsigned y0, y1;
          tf2x32(sk0, sk1, 0u, (unsigned)r, y0, y1);
          float u   = u01(y0 ^ y1);
          float act = (u < pi) ? 1.0f : 0.0f;
          out[(size_t)step * DIM + r]                       = act;
          out[(size_t)SEQ * DIM + (size_t)step * DIM + r]   = pi;
          __stcg(&g_x[r], act * __ldg(&A[r]));
        } else {
          int gi = li - 16;
          int q = gi >> 4, i2 = gi & 15;
          int row = q * HID + b * 16 + i2;
          gsum[gi] = s + __ldg(&b_ih[row]) + __ldg(&b_hh[row]);
        }
      }
    }
    grid_barrier();  // x fully written by all CTAs

    // =========== Phase B: gates += W_ih @ x (sparse column gather), cell update ===========
    for (int i = tid; i < DIM; i += NTHR) x_s[i] = __ldcg(&g_x[i]);
    __syncthreads();

    {
      const int seg = tid >> 6;           // 16 j-segments of 128
      const int g   = tid & 63;           // 64 owned gate rows
      const int q = g >> 4, i2 = g & 15;
      const int col = q * HID + b * 16 + i2;
      float acc = 0.0f;
      const int j0 = seg * 128;
      #pragma unroll 4
      for (int j = j0; j < j0 + 128; ++j) {
        float xv = x_s[j];
        if (xv != 0.0f) acc += xv * g_Wt[(size_t)j * GAT + col];
      }
      part[seg][g] = acc;                 // deterministic reduction (no atomics)
    }
    __syncthreads();
    if (tid < 64) {
      float s2 = gsum[tid];
      #pragma unroll
      for (int s3 = 0; s3 < 16; ++s3) s2 += part[s3][tid];
      gsum[tid] = s2;
    }
    __syncthreads();

    if (tid < UPC) {
      float ig = gsum[tid];
      float fg = gsum[16 + tid];
      float gg = gsum[32 + tid];
      float og = gsum[48 + tid];
      float cn = sigf(fg) * c_s[tid] + sigf(ig) * tanhf(gg);
      float hn = sigf(og) * tanhf(cn);
      c_s[tid] = cn;
      __stcg(&g_h[b * 16 + tid], hn);
    }
    grid_barrier();  // h visible for next step
  }
}

extern "C" void kernel_launch(void* const* d_in, const int* in_sizes, int n_in,
                              void* d_out, int out_size) {
  (void)in_sizes; (void)n_in; (void)out_size;
  lstm_policy_kernel<<<NCTA, NTHR>>>(
      (const float*)d_in[0],  // A
      (const float*)d_in[1],  // W_ih
      (const float*)d_in[2],  // W_hh
      (const float*)d_in[3],  // b_ih
      (const float*)d_in[4],  // b_hh
      (const float*)d_in[5],  // V_w
      (const float*)d_in[6],  // V_b
      (const float*)d_in[7],  // temperature
      (float*)d_out);
}

// round 3
// speedup vs baseline: 1.7123x; 1.7123x over previous
#include <cuda_runtime.h>

#define SEQ  256
#define HID  2048
#define DIM  2048
#define GAT  8192   // 4*HID
#define NCTA 128
#define NTHR 1024
#define UPC  16     // hidden units owned per CTA (128*16 = 2048)

// ---- persistent device state (static allocation: allowed) ----
__device__ float g_Wt[(size_t)DIM * GAT];   // W_ih transposed: [DIM][GAT], 64MB
__device__ float g_h[HID];
__device__ float g_x[DIM];
__device__ unsigned int g_bar;
__device__ volatile unsigned int g_gen;

// ---- JAX threefry2x32 (exact rounds, partitionable counter layout) ----
__device__ __forceinline__ void tf2x32(unsigned k0, unsigned k1,
                                       unsigned x0, unsigned x1,
                                       unsigned &o0, unsigned &o1) {
  unsigned ks2 = k0 ^ k1 ^ 0x1BD11BDAu;
#define TFR(r) { x0 += x1; x1 = (x1 << (r)) | (x1 >> (32 - (r))); x1 ^= x0; }
  x0 += k0; x1 += k1;
  TFR(13) TFR(15) TFR(26) TFR(6)   x0 += k1;  x1 += ks2 + 1u;
  TFR(17) TFR(29) TFR(16) TFR(24)  x0 += ks2; x1 += k0 + 2u;
  TFR(13) TFR(15) TFR(26) TFR(6)   x0 += k0;  x1 += k1 + 3u;
  TFR(17) TFR(29) TFR(16) TFR(24)  x0 += k1;  x1 += ks2 + 4u;
  TFR(13) TFR(15) TFR(26) TFR(6)   x0 += ks2; x1 += k0 + 5u;
#undef TFR
  o0 = x0; o1 = x1;
}

__device__ __forceinline__ float u01(unsigned bits) {
  return __uint_as_float((bits >> 9) | 0x3f800000u) - 1.0f;
}

__device__ __forceinline__ float sigf(float v) {
  return 1.0f / (1.0f + expf(-v));
}

// generation-based grid barrier (all CTAs co-resident by construction)
__device__ __forceinline__ void grid_barrier() {
  __threadfence();
  __syncthreads();
  if (threadIdx.x == 0) {
    unsigned gen = g_gen;
    if (atomicAdd(&g_bar, 1u) == gridDim.x - 1u) {
      g_bar = 0u;
      __threadfence();
      g_gen = gen + 1u;
    } else {
      while (g_gen == gen) { __nanosleep(20); }
    }
  }
  __syncthreads();
}

extern "C" __global__ void __launch_bounds__(NTHR, 1)
lstm_policy_kernel(const float* __restrict__ A,
                   const float* __restrict__ W_ih,
                   const float* __restrict__ W_hh,
                   const float* __restrict__ b_ih,
                   const float* __restrict__ b_hh,
                   const float* __restrict__ V_w,
                   const float* __restrict__ V_b,
                   const float* __restrict__ temp,
                   float* __restrict__ out)
{
  const int b    = blockIdx.x;
  const int tid  = threadIdx.x;
  const int lane = tid & 31;
  const int w    = tid >> 5;

  __shared__ float h_s[HID];          // 8KB
  __shared__ float x_s[DIM];          // 8KB
  __shared__ int   nzi[DIM];          // 8KB  compacted nonzero indices
  __shared__ float nzv[DIM];          // 8KB  compacted nonzero values
  __shared__ int   wcnt[32];
  __shared__ int   woff[33];
  __shared__ float gsum[64];          // gate pre-activations for owned units
  __shared__ float c_s[UPC];          // persistent cell state (owned units)
  __shared__ float part[16][64];      // deterministic phase-B reduction
  __shared__ float tile[32][33];      // transpose staging

  // ---- one-time (per launch) transpose W_ih[GAT][DIM] -> g_Wt[DIM][GAT] ----
  {
    const int ty = tid >> 5, tx = tid & 31;
    const int ntiles = (GAT / 32) * (DIM / 32);  // 16384
    for (int t = b; t < ntiles; t += gridDim.x) {
      int tr = t / (DIM / 32), tc = t % (DIM / 32);
      int r0 = tr * 32, j0 = tc * 32;
      tile[ty][tx] = W_ih[(size_t)(r0 + ty) * DIM + (j0 + tx)];
      __syncthreads();
      g_Wt[(size_t)(j0 + ty) * GAT + (r0 + tx)] = tile[tx][ty];
      __syncthreads();
    }
  }
  if (tid < UPC) c_s[tid] = 0.0f;
  grid_barrier();

  const float temperature = __ldg(temp);

  for (int step = 0; step < SEQ; ++step) {
    // per-step subkey (partitionable split): keys[t] = threefry(key, (0, t))
    unsigned sk0, sk1;
    tf2x32(0u, 42u, 0u, (unsigned)step, sk0, sk1);

    // ============ Phase A: z = V_w@h (16 rows) ; gates_hh = W_hh@h (64 rows) ============
    for (int i = tid; i < HID; i += NTHR)
      h_s[i] = (step == 0) ? 0.0f : __ldcg(&g_h[i]);
    __syncthreads();

    const float4* H4 = (const float4*)h_s;

    // virtual row index li -> global row pointer
    auto rowptr = [&](int li) -> const float* {
      if (li < 16) return V_w + (size_t)(b * 16 + li) * DIM;
      int gi = li - 16; int q_ = gi >> 4, i2_ = gi & 15;
      return W_hh + (size_t)(q_ * HID + b * 16 + i2_) * DIM;
    };
    // handle a finished dot product for virtual row li (lane 0 only)
    auto dispatch = [&](int li, float s) {
      if (li < 16) {
        int r = b * 16 + li;
        float z  = temperature * (s + __ldg(&V_b[r]));
        float pi = sigf(z);
        unsigned y0, y1;
        tf2x32(sk0, sk1, 0u, (unsigned)r, y0, y1);
        float u   = u01(y0 ^ y1);
        float act = (u < pi) ? 1.0f : 0.0f;
        out[(size_t)step * DIM + r]                     = act;
        out[(size_t)SEQ * DIM + (size_t)step * DIM + r] = pi;
        __stcg(&g_x[r], act * __ldg(&A[r]));
      } else {
        int gi = li - 16; int q_ = gi >> 4, i2_ = gi & 15;
        int row = q_ * HID + b * 16 + i2_;
        gsum[gi] = s + __ldg(&b_ih[row]) + __ldg(&b_hh[row]);
      }
    };

    // paired rows (w, w+32): 2 accumulators -> 2x outstanding loads
    {
      const float4* Ra = (const float4*)rowptr(w);
      const float4* Rb = (const float4*)rowptr(w + 32);
      float sA = 0.0f, sB = 0.0f;
      #pragma unroll
      for (int k = 0; k < 16; ++k) {
        float4 a  = __ldg(&Ra[k * 32 + lane]);
        float4 bb = __ldg(&Rb[k * 32 + lane]);
        float4 hh = H4[k * 32 + lane];
        sA += a.x  * hh.x + a.y  * hh.y + a.z  * hh.z + a.w  * hh.w;
        sB += bb.x * hh.x + bb.y * hh.y + bb.z * hh.z + bb.w * hh.w;
      }
      #pragma unroll
      for (int o = 16; o > 0; o >>= 1) {
        sA += __shfl_xor_sync(0xffffffffu, sA, o);
        sB += __shfl_xor_sync(0xffffffffu, sB, o);
      }
      if (lane == 0) { dispatch(w, sA); dispatch(w + 32, sB); }
    }
    // leftover rows 64..79 on warps 0..15
    if (w < 16) {
      const float4* Rc = (const float4*)rowptr(64 + w);
      float sC = 0.0f;
      #pragma unroll
      for (int k = 0; k < 16; ++k) {
        float4 cc = __ldg(&Rc[k * 32 + lane]);
        float4 hh = H4[k * 32 + lane];
        sC += cc.x * hh.x + cc.y * hh.y + cc.z * hh.z + cc.w * hh.w;
      }
      #pragma unroll
      for (int o = 16; o > 0; o >>= 1) sC += __shfl_xor_sync(0xffffffffu, sC, o);
      if (lane == 0) dispatch(64 + w, sC);
    }
    grid_barrier();  // x fully written by all CTAs

    // ============ Phase B: gates += W_ih @ x via compacted nonzero gather ============
    for (int i = tid; i < DIM; i += NTHR) x_s[i] = __ldcg(&g_x[i]);
    __syncthreads();

    // deterministic compaction: warp w owns elements [w*64, w*64+64)
    {
      int base = w * 64;
      float v0 = x_s[base + lane];
      float v1 = x_s[base + 32 + lane];
      unsigned b0 = __ballot_sync(0xffffffffu, v0 != 0.0f);
      unsigned b1 = __ballot_sync(0xffffffffu, v1 != 0.0f);
      if (lane == 0) wcnt[w] = __popc(b0) + __popc(b1);
      __syncthreads();
      if (w == 0) {
        int c = wcnt[lane];
        int xs = c;
        #pragma unroll
        for (int o = 1; o < 32; o <<= 1) {
          int y = __shfl_up_sync(0xffffffffu, xs, o);
          if (lane >= o) xs += y;
        }
        woff[lane] = xs - c;          // exclusive prefix
        if (lane == 31) woff[32] = xs; // total count
      }
      __syncthreads();
      int off = woff[w];
      unsigned mask = (1u << lane) - 1u;
      if (v0 != 0.0f) {
        int p = off + __popc(b0 & mask);
        nzi[p] = base + lane; nzv[p] = v0;
      }
      if (v1 != 0.0f) {
        int p = off + __popc(b0) + __popc(b1 & mask);
        nzi[p] = base + 32 + lane; nzv[p] = v1;
      }
      __syncthreads();
    }
    const int len = woff[32];

    // gather: seg strides the compacted list; streaming loads keep V_w/W_hh in L2
    {
      const int seg = tid >> 6;           // 16 segments
      const int g   = tid & 63;           // 64 owned gate rows
      const int q_ = g >> 4, i2_ = g & 15;
      const size_t col = (size_t)(q_ * HID + b * 16 + i2_);
      float acc = 0.0f;
      #pragma unroll 4
      for (int k = seg; k < len; k += 16) {
        acc += nzv[k] * __ldcs(&g_Wt[(size_t)nzi[k] * GAT + col]);
      }
      part[seg][g] = acc;                 // deterministic reduction (no atomics)
    }
    __syncthreads();
    if (tid < 64) {
      float s2 = gsum[tid];
      #pragma unroll
      for (int s3 = 0; s3 < 16; ++s3) s2 += part[s3][tid];
      gsum[tid] = s2;
    }
    __syncthreads();

    if (tid < UPC) {
      float ig = gsum[tid];
      float fg = gsum[16 + tid];
      float gg = gsum[32 + tid];
      float og = gsum[48 + tid];
      float cn = sigf(fg) * c_s[tid] + sigf(ig) * tanhf(gg);
      float hn = sigf(og) * tanhf(cn);
      c_s[tid] = cn;
      __stcg(&g_h[b * 16 + tid], hn);
    }
    grid_barrier();  // h visible for next step
  }
}

extern "C" void kernel_launch(void* const* d_in, const int* in_sizes, int n_in,
                              void* d_out, int out_size) {
  (void)in_sizes; (void)n_in; (void)out_size;
  lstm_policy_kernel<<<NCTA, NTHR>>>(
      (const float*)d_in[0],  // A
      (const float*)d_in[1],  // W_ih
      (const float*)d_in[2],  // W_hh
      (const float*)d_in[3],  // b_ih
      (const float*)d_in[4],  // b_hh
      (const float*)d_in[5],  // V_w
      (const float*)d_in[6],  // V_b
      (const float*)d_in[7],  // temperature
      (float*)d_out);
}